// round 11
// baseline (speedup 1.0000x reference)
#include <cuda_runtime.h>
#include <cstddef>

// Problem constants (fixed by the reference)
#define BB 8
#define DD 32
#define NPIX 262144          // 512*512
#define KK 16

// Pass-1 tiling: 64 pixel-chunks x 2 d-groups x 8 images = 1024 blocks
#define P1_CHUNK  4096
#define P1_NCHUNK (NPIX / P1_CHUNK)    // 64

// Pass-2 tiling: one float4 (4 pixels) per thread
#define P2_TPB    256
#define P2_BLOCKS (NPIX / 4 / P2_TPB)  // 256 blocks per image

// Scratch (no cudaMalloc allowed). Partials fully overwritten each launch.
__device__ float g_part[BB * P1_NCHUNK * KK * DD];   // per-chunk partial sums
__device__ float g_cntp[BB * P1_NCHUNK * KK];        // per-chunk partial counts
__device__ float g_counts[BB * KK];
__device__ float g_means[BB * KK * DD];

// ---------------------------------------------------------------------------
// Pass 1: per-image, per-chunk partial segment sums.
// Block = 256 threads = 8 warps; warp w owns TWO planes d0 = dg*16 + w and
// d0+8 over a 4096-px chunk. Bins are float2 (one component per plane):
// one label -> 1 LDS.64 + 2 FADD + 1 STS.64 covering TWO elements, halving
// the smem op stream (the binding resource at ~4 cyc/op multi-warp floor).
// 34 KB static smem, 256 thr -> 6 blocks/SM = 48 warps (75% occupancy).
// Labels via __ldg int4 (no smem alias barrier; L1-hot across the 8 warps).
// ---------------------------------------------------------------------------
__global__ __launch_bounds__(256, 6) void k_pass1(const float* __restrict__ emb,
                                                  const int* __restrict__ gt,
                                                  float* out) {
    __shared__ float2 acc2[8 * KK * 32];         // [w][k][lane]  32 KB
    __shared__ float  cnt[KK * 32];              // [k][lane]      2 KB

    const int b  = blockIdx.z;
    const int dg = blockIdx.y;                   // d group: 0 or 1
    const int c  = blockIdx.x;                   // chunk
    const int p0 = c * P1_CHUNK;
    const int tid = threadIdx.x;
    const int w   = tid >> 5;
    const int lane = tid & 31;
    const int d0 = dg * 16 + w;                  // planes d0 and d0+8

    if (b == 0 && dg == 0 && c == 0 && tid == 0) out[0] = 0.0f;

    // Per-warp zeroing of this warp's own bins (no block sync needed).
    float2* aw2 = acc2 + (w * KK) * 32 + lane;
    #pragma unroll
    for (int k = 0; k < KK; k++) aw2[k * 32] = make_float2(0.f, 0.f);

    const bool docnt = (dg == 0) && (w == 0);
    float* cw = cnt + lane;
    if (docnt) {
        #pragma unroll
        for (int k = 0; k < KK; k++) cw[k * 32] = 0.0f;
    }
    __syncwarp();

    const float4* eA = (const float4*)(emb + ((size_t)(b * DD + d0)) * NPIX + p0);
    const float4* eB = (const float4*)(emb + ((size_t)(b * DD + d0 + 8)) * NPIX + p0);
    const int4*   g4 = (const int4*)(gt + (size_t)b * NPIX + p0);

    #define RMW2(K, A, B) do {                                           \
        float2 t_ = aw2[(K) * 32];                                       \
        t_.x += (A); t_.y += (B);                                        \
        aw2[(K) * 32] = t_;                                              \
    } while (0)

    // 1024 float4-groups per chunk; lane handles 32 (one per iteration),
    // each covering 4 pixels x 2 planes = 8 element-adds via 4 RMW2s.
    #pragma unroll 1
    for (int i = 0; i < 32; i++) {
        const int idx = i * 32 + lane;
        float4 va = __ldcs(&eA[idx]);
        float4 vb = __ldcs(&eB[idx]);
        int4   l  = __ldg(&g4[idx]);

        RMW2(l.x, va.x, vb.x);
        RMW2(l.y, va.y, vb.y);
        RMW2(l.z, va.z, vb.z);
        RMW2(l.w, va.w, vb.w);

        if (docnt) {
            cw[l.x * 32] += 1.0f;
            cw[l.y * 32] += 1.0f;
            cw[l.z * 32] += 1.0f;
            cw[l.w * 32] += 1.0f;
        }
    }
    #undef RMW2
    __syncwarp();

    // Epilogue: k-row = 32 float2 = 256B contiguous. 2 lanes per k-row, each
    // reads 8 float4 (128B half-row), separates plane-A/plane-B components,
    // 1 shuffle, 2 STGs (no atomics). Runs once per block; conflicts ok.
    {
        const int k = lane >> 1;
        const int h = lane & 1;
        const float4* row = (const float4*)(acc2 + (w * KK + k) * 32) + h * 8;
        float sx = 0.0f, sy = 0.0f;
        #pragma unroll
        for (int j = 0; j < 8; j++) {
            float4 v = row[j];
            sx += v.x + v.z;
            sy += v.y + v.w;
        }
        sx += __shfl_down_sync(0xffffffffu, sx, 1);
        sy += __shfl_down_sync(0xffffffffu, sy, 1);
        if (h == 0) {
            float* gp = &g_part[(((b * P1_NCHUNK + c) * KK + k) * DD)];
            gp[d0]     = sx;
            gp[d0 + 8] = sy;
        }
    }
    if (docnt) {
        const int k = lane >> 1;
        const int h = lane & 1;
        const float4* row = (const float4*)(cnt + (k << 5) + (h << 4));
        float4 r0 = row[0], r1 = row[1], r2 = row[2], r3 = row[3];
        float s = ((r0.x + r0.y) + (r0.z + r0.w)) + ((r1.x + r1.y) + (r1.z + r1.w))
                + ((r2.x + r2.y) + (r2.z + r2.w)) + ((r3.x + r3.y) + (r3.z + r3.w));
        s += __shfl_down_sync(0xffffffffu, s, 1);
        if (h == 0)
            g_cntp[(b * P1_NCHUNK + c) * KK + k] = s;
    }
}

// ---------------------------------------------------------------------------
// Finalize: reduce partials -> counts & means; pairwise push loss; reg loss.
// One block per image.
// ---------------------------------------------------------------------------
__global__ __launch_bounds__(256) void k_finalize(float* out) {
    __shared__ float m[KK * 33];    // padded means
    __shared__ float cs[KK];
    __shared__ float red[256];

    const int b = blockIdx.x;
    const int tid = threadIdx.x;

    if (tid < KK) {
        float s = 0.0f;
        #pragma unroll 4
        for (int c = 0; c < P1_NCHUNK; c++)
            s += g_cntp[(b * P1_NCHUNK + c) * KK + tid];
        float cv = fmaxf(s, 1.0f);
        cs[tid] = cv;
        g_counts[b * KK + tid] = cv;
    }
    __syncthreads();

    for (int j = tid; j < KK * DD; j += 256) {
        int k = j >> 5, d = j & 31;
        float s = 0.0f;
        #pragma unroll 4
        for (int c = 0; c < P1_NCHUNK; c++)
            s += g_part[(((b * P1_NCHUNK + c) * KK + k) * DD) + d];
        float mean = s / cs[k];
        g_means[(b * KK + k) * DD + d] = mean;
        m[k * 33 + d] = mean;
    }
    __syncthreads();

    // Pairwise hinge on cluster-mean distances: thread -> (i,j), upper tri only.
    const int i = tid >> 4;
    const int j = tid & 15;
    float contrib = 0.0f;
    if (j > i) {
        float d2 = 0.0f;
        #pragma unroll
        for (int d = 0; d < DD; d++) {
            float df = m[i * 33 + d] - m[j * 33 + d];
            d2 = fmaf(df, df, d2);
        }
        float pd = sqrtf(d2);             // i<j: diagonal eye irrelevant
        float h = fmaxf(3.0f - pd, 0.0f); // 2 * DIST_THETA = 3.0
        contrib = h * h;
    }

    float reg = 0.0f;
    if (tid < KK) {
        float n2 = 0.0f;
        #pragma unroll
        for (int d = 0; d < DD; d++) {
            float v = m[tid * 33 + d];
            n2 = fmaf(v, v, n2);
        }
        reg = sqrtf(n2);
    }

    red[tid] = contrib * (1.0f / (KK * (KK - 1))) + 0.001f * reg * (1.0f / KK);
    __syncthreads();
    for (int off = 128; off; off >>= 1) {
        if (tid < off) red[tid] += red[tid + off];
        __syncthreads();
    }
    if (tid == 0) atomicAdd(out, red[0] * (1.0f / BB));
}

// ---------------------------------------------------------------------------
// Pass 2: per-pixel hinge variance loss, folded directly into the scalar.
// One float4 (4 consecutive pixels) per thread; batched LDG.128s.
// ---------------------------------------------------------------------------
__global__ __launch_bounds__(P2_TPB) void k_pass2(const float* __restrict__ emb,
                                                  const int* __restrict__ gt,
                                                  float* out) {
    __shared__ float m[KK * 33];
    __shared__ float wk[KK];
    __shared__ float red[P2_TPB / 32];

    const int b  = blockIdx.y;
    const int tid = threadIdx.x;
    const int lane = tid & 31;
    const int w = tid >> 5;
    const int p4 = blockIdx.x * P2_TPB + tid;    // float4 index

    for (int j = tid; j < KK * DD; j += P2_TPB)
        m[(j / DD) * 33 + (j % DD)] = g_means[b * KK * DD + j];
    if (tid < KK)
        wk[tid] = 1.0f / ((float)KK * fmaxf(g_counts[b * KK + tid], 1.0f));
    __syncthreads();

    const float4* e4 = (const float4*)(emb + (size_t)b * DD * NPIX);
    const int4 kk = ((const int4*)(gt + (size_t)b * NPIX))[p4];

    const float* m0 = m + kk.x * 33;
    const float* m1 = m + kk.y * 33;
    const float* m2 = m + kk.z * 33;
    const float* m3 = m + kk.w * 33;

    float a0 = 0.0f, a1 = 0.0f, a2 = 0.0f, a3 = 0.0f;
    #pragma unroll
    for (int g = 0; g < 4; g++) {
        float4 v[8];
        #pragma unroll
        for (int j = 0; j < 8; j++)
            v[j] = __ldcs(&e4[(size_t)(g * 8 + j) * (NPIX / 4) + p4]);
        #pragma unroll
        for (int j = 0; j < 8; j++) {
            const int d = g * 8 + j;
            float t;
            t = v[j].x - m0[d]; a0 = fmaf(t, t, a0);
            t = v[j].y - m1[d]; a1 = fmaf(t, t, a1);
            t = v[j].z - m2[d]; a2 = fmaf(t, t, a2);
            t = v[j].w - m3[d]; a3 = fmaf(t, t, a3);
        }
    }

    float h, lacc = 0.0f;
    h = fmaxf(sqrtf(a0) - 0.5f, 0.0f); lacc = fmaf(h * h, wk[kk.x], lacc);
    h = fmaxf(sqrtf(a1) - 0.5f, 0.0f); lacc = fmaf(h * h, wk[kk.y], lacc);
    h = fmaxf(sqrtf(a2) - 0.5f, 0.0f); lacc = fmaf(h * h, wk[kk.z], lacc);
    h = fmaxf(sqrtf(a3) - 0.5f, 0.0f); lacc = fmaf(h * h, wk[kk.w], lacc);

    #pragma unroll
    for (int off = 16; off; off >>= 1)
        lacc += __shfl_down_sync(0xffffffffu, lacc, off);
    if (lane == 0) red[w] = lacc;
    __syncthreads();
    if (tid == 0) {
        float s = 0.0f;
        #pragma unroll
        for (int i = 0; i < P2_TPB / 32; i++) s += red[i];
        atomicAdd(out, s * (1.0f / BB));
    }
}

// ---------------------------------------------------------------------------
extern "C" void kernel_launch(void* const* d_in, const int* in_sizes, int n_in,
                              void* d_out, int out_size) {
    int ei = 0, gi = 1;
    // Defensive: identify inputs by size (embeddings = 67108864, gt = 2097152)
    if (n_in >= 2 && in_sizes[0] == BB * NPIX) { ei = 1; gi = 0; }

    const float* emb = (const float*)d_in[ei];
    const int*   gt  = (const int*)d_in[gi];
    float* out = (float*)d_out;

    k_pass1<<<dim3(P1_NCHUNK, 2, BB), 256>>>(emb, gt, out);
    k_finalize<<<BB, 256>>>(out);
    k_pass2<<<dim3(P2_BLOCKS, BB), P2_TPB>>>(emb, gt, out);
}

// round 12
// speedup vs baseline: 1.3984x; 1.3984x over previous
#include <cuda_runtime.h>
#include <cstddef>

// Problem constants (fixed by the reference)
#define BB 8
#define DD 32
#define NPIX 262144          // 512*512
#define KK 16

// Pass-1 tiling: 32 pixel-chunks x 2 d-groups x 8 images = 512 blocks
#define P1_CHUNK  8192
#define P1_NCHUNK (NPIX / P1_CHUNK)    // 32

// Pass-2 tiling: one float4 (4 pixels) per thread
#define P2_TPB    256
#define P2_BLOCKS (NPIX / 4 / P2_TPB)  // 256 blocks per image

// Scratch (no cudaMalloc allowed). Partials fully overwritten each launch.
__device__ float g_part[BB * P1_NCHUNK * KK * DD];   // per-chunk partial sums
__device__ float g_cntp[BB * P1_NCHUNK * KK];        // per-chunk partial counts
__device__ float g_counts[BB * KK];
__device__ float g_means[BB * KK * DD];

// ---------------------------------------------------------------------------
// Pass 1: per-image, per-chunk partial segment sums. (R8 structure verbatim.)
// Block = 512 threads = 16 warps; warp w owns plane d = dg*16 + w over the
// whole 8192-px chunk. Software-pipelined (distance 1).
// KEY CHANGE vs R8: embeddings are loaded with DEFAULT policy (__ldg), not
// __ldcs. Pass1 is the FIRST reader; leaving the stream L2-resident lets
// pass2 hit ~47% of its 268 MB re-read in the 126 MB L2 instead of DRAM.
// Per-lane privatized smem bins (stride 32): LDS/FADD/STS conflict-free.
// ---------------------------------------------------------------------------
__global__ __launch_bounds__(512) void k_pass1(const float* __restrict__ emb,
                                               const int* __restrict__ gt,
                                               float* out) {
    __shared__ float acc[16 * KK * 32];          // [w][k][lane]  32 KB
    __shared__ float cnt[KK * 32];               // [k][lane]      2 KB
    __shared__ unsigned int labw[P1_CHUNK / 4];  // packed 4x u8    8 KB

    const int b  = blockIdx.z;
    const int dg = blockIdx.y;                   // d group: 0 or 1
    const int c  = blockIdx.x;                   // chunk
    const int p0 = c * P1_CHUNK;
    const int tid = threadIdx.x;
    const int w   = tid >> 5;
    const int lane = tid & 31;
    const int d = dg * 16 + w;

    if (b == 0 && dg == 0 && c == 0 && tid == 0) out[0] = 0.0f;

    for (int j = tid; j < 16 * KK * 32; j += 512) acc[j] = 0.0f;
    if (tid < KK * 32) cnt[tid] = 0.0f;

    // Stage labels once (int4 -> packed u8x4): 2048 words (default policy)
    const int4* g4 = (const int4*)(gt + (size_t)b * NPIX + p0);
    for (int j = tid; j < P1_CHUNK / 4; j += 512) {
        int4 t = g4[j];
        labw[j] = (unsigned)t.x | ((unsigned)t.y << 8) |
                  ((unsigned)t.z << 16) | ((unsigned)t.w << 24);
    }
    __syncthreads();

    const float4* e4 = (const float4*)(emb + ((size_t)(b * DD + d)) * NPIX + p0);
    const bool docnt = (dg == 0) && (w == 0);

    float* aw = acc + (w * KK) * 32 + lane;
    float* cw = cnt + lane;

    #define RMW(V, KW) do {                                             \
        unsigned kw_ = (KW);                                            \
        aw[(int)(kw_ & 15u) * 32]         += (V).x;                     \
        aw[(int)((kw_ >> 8) & 15u) * 32]  += (V).y;                     \
        aw[(int)((kw_ >> 16) & 15u) * 32] += (V).z;                     \
        aw[(int)(kw_ >> 24) * 32]         += (V).w;                     \
    } while (0)
    #define CNT(KW) do {                                                \
        unsigned kw_ = (KW);                                            \
        cw[(int)(kw_ & 15u) * 32]         += 1.0f;                      \
        cw[(int)((kw_ >> 8) & 15u) * 32]  += 1.0f;                      \
        cw[(int)((kw_ >> 16) & 15u) * 32] += 1.0f;                      \
        cw[(int)(kw_ >> 24) * 32]         += 1.0f;                      \
    } while (0)

    // 2048 float4s per plane-chunk per warp; 64 per lane, two per iteration.
    // Software pipeline, prefetch distance 1. Default-policy loads (L2-keep).
    float4 va = __ldg(&e4[lane]);
    float4 vb = __ldg(&e4[lane + 32]);
    unsigned ka = labw[lane];
    unsigned kb = labw[lane + 32];

    #pragma unroll 1
    for (int i = 0; i < 31; i++) {
        const int nidx = (i + 1) * 64 + lane;
        float4 na = __ldg(&e4[nidx]);
        float4 nb = __ldg(&e4[nidx + 32]);
        unsigned nka = labw[nidx];
        unsigned nkb = labw[nidx + 32];

        RMW(va, ka);
        RMW(vb, kb);
        if (docnt) { CNT(ka); CNT(kb); }

        va = na; vb = nb; ka = nka; kb = nkb;
    }
    RMW(va, ka);
    RMW(vb, kb);
    if (docnt) { CNT(ka); CNT(kb); }
    #undef RMW
    #undef CNT
    __syncwarp();

    // Epilogue: rows acc[w][k][0..31] are contiguous 128B. 2 lanes per k-row,
    // each reads 4 float4, sum, 1 shuffle, STG (no atomics).
    {
        const int k = lane >> 1;
        const int h = lane & 1;
        const float4* row = (const float4*)(acc + ((w * KK + k) << 5) + (h << 4));
        float4 r0 = row[0], r1 = row[1], r2 = row[2], r3 = row[3];
        float s = ((r0.x + r0.y) + (r0.z + r0.w)) + ((r1.x + r1.y) + (r1.z + r1.w))
                + ((r2.x + r2.y) + (r2.z + r2.w)) + ((r3.x + r3.y) + (r3.z + r3.w));
        s += __shfl_down_sync(0xffffffffu, s, 1);
        if (h == 0)
            g_part[(((b * P1_NCHUNK + c) * KK + k) * DD) + d] = s;
    }
    if (docnt) {
        const int k = lane >> 1;
        const int h = lane & 1;
        const float4* row = (const float4*)(cnt + (k << 5) + (h << 4));
        float4 r0 = row[0], r1 = row[1], r2 = row[2], r3 = row[3];
        float s = ((r0.x + r0.y) + (r0.z + r0.w)) + ((r1.x + r1.y) + (r1.z + r1.w))
                + ((r2.x + r2.y) + (r2.z + r2.w)) + ((r3.x + r3.y) + (r3.z + r3.w));
        s += __shfl_down_sync(0xffffffffu, s, 1);
        if (h == 0)
            g_cntp[(b * P1_NCHUNK + c) * KK + k] = s;
    }
}

// ---------------------------------------------------------------------------
// Finalize: reduce partials -> counts & means; pairwise push loss; reg loss.
// One block per image.
// ---------------------------------------------------------------------------
__global__ __launch_bounds__(256) void k_finalize(float* out) {
    __shared__ float m[KK * 33];    // padded means
    __shared__ float cs[KK];
    __shared__ float red[256];

    const int b = blockIdx.x;
    const int tid = threadIdx.x;

    if (tid < KK) {
        float s = 0.0f;
        #pragma unroll 4
        for (int c = 0; c < P1_NCHUNK; c++)
            s += g_cntp[(b * P1_NCHUNK + c) * KK + tid];
        float cv = fmaxf(s, 1.0f);
        cs[tid] = cv;
        g_counts[b * KK + tid] = cv;
    }
    __syncthreads();

    for (int j = tid; j < KK * DD; j += 256) {
        int k = j >> 5, d = j & 31;
        float s = 0.0f;
        #pragma unroll 4
        for (int c = 0; c < P1_NCHUNK; c++)
            s += g_part[(((b * P1_NCHUNK + c) * KK + k) * DD) + d];
        float mean = s / cs[k];
        g_means[(b * KK + k) * DD + d] = mean;
        m[k * 33 + d] = mean;
    }
    __syncthreads();

    // Pairwise hinge on cluster-mean distances: thread -> (i,j), upper tri only.
    const int i = tid >> 4;
    const int j = tid & 15;
    float contrib = 0.0f;
    if (j > i) {
        float d2 = 0.0f;
        #pragma unroll
        for (int d = 0; d < DD; d++) {
            float df = m[i * 33 + d] - m[j * 33 + d];
            d2 = fmaf(df, df, d2);
        }
        float pd = sqrtf(d2);             // i<j: diagonal eye irrelevant
        float h = fmaxf(3.0f - pd, 0.0f); // 2 * DIST_THETA = 3.0
        contrib = h * h;
    }

    float reg = 0.0f;
    if (tid < KK) {
        float n2 = 0.0f;
        #pragma unroll
        for (int d = 0; d < DD; d++) {
            float v = m[tid * 33 + d];
            n2 = fmaf(v, v, n2);
        }
        reg = sqrtf(n2);
    }

    red[tid] = contrib * (1.0f / (KK * (KK - 1))) + 0.001f * reg * (1.0f / KK);
    __syncthreads();
    for (int off = 128; off; off >>= 1) {
        if (tid < off) red[tid] += red[tid + off];
        __syncthreads();
    }
    if (tid == 0) atomicAdd(out, red[0] * (1.0f / BB));
}

// ---------------------------------------------------------------------------
// Pass 2: per-pixel hinge variance loss, folded directly into the scalar.
// One float4 (4 consecutive pixels) per thread; batched LDG.128s.
// __ldcs here is correct: pass2 is the LAST consumer (evict-first).
// ---------------------------------------------------------------------------
__global__ __launch_bounds__(P2_TPB) void k_pass2(const float* __restrict__ emb,
                                                  const int* __restrict__ gt,
                                                  float* out) {
    __shared__ float m[KK * 33];
    __shared__ float wk[KK];
    __shared__ float red[P2_TPB / 32];

    const int b  = blockIdx.y;
    const int tid = threadIdx.x;
    const int lane = tid & 31;
    const int w = tid >> 5;
    const int p4 = blockIdx.x * P2_TPB + tid;    // float4 index

    for (int j = tid; j < KK * DD; j += P2_TPB)
        m[(j / DD) * 33 + (j % DD)] = g_means[b * KK * DD + j];
    if (tid < KK)
        wk[tid] = 1.0f / ((float)KK * fmaxf(g_counts[b * KK + tid], 1.0f));
    __syncthreads();

    const float4* e4 = (const float4*)(emb + (size_t)b * DD * NPIX);
    const int4 kk = ((const int4*)(gt + (size_t)b * NPIX))[p4];

    const float* m0 = m + kk.x * 33;
    const float* m1 = m + kk.y * 33;
    const float* m2 = m + kk.z * 33;
    const float* m3 = m + kk.w * 33;

    float a0 = 0.0f, a1 = 0.0f, a2 = 0.0f, a3 = 0.0f;
    #pragma unroll
    for (int g = 0; g < 4; g++) {
        float4 v[8];
        #pragma unroll
        for (int j = 0; j < 8; j++)
            v[j] = __ldcs(&e4[(size_t)(g * 8 + j) * (NPIX / 4) + p4]);
        #pragma unroll
        for (int j = 0; j < 8; j++) {
            const int d = g * 8 + j;
            float t;
            t = v[j].x - m0[d]; a0 = fmaf(t, t, a0);
            t = v[j].y - m1[d]; a1 = fmaf(t, t, a1);
            t = v[j].z - m2[d]; a2 = fmaf(t, t, a2);
            t = v[j].w - m3[d]; a3 = fmaf(t, t, a3);
        }
    }

    float h, lacc = 0.0f;
    h = fmaxf(sqrtf(a0) - 0.5f, 0.0f); lacc = fmaf(h * h, wk[kk.x], lacc);
    h = fmaxf(sqrtf(a1) - 0.5f, 0.0f); lacc = fmaf(h * h, wk[kk.y], lacc);
    h = fmaxf(sqrtf(a2) - 0.5f, 0.0f); lacc = fmaf(h * h, wk[kk.z], lacc);
    h = fmaxf(sqrtf(a3) - 0.5f, 0.0f); lacc = fmaf(h * h, wk[kk.w], lacc);

    #pragma unroll
    for (int off = 16; off; off >>= 1)
        lacc += __shfl_down_sync(0xffffffffu, lacc, off);
    if (lane == 0) red[w] = lacc;
    __syncthreads();
    if (tid == 0) {
        float s = 0.0f;
        #pragma unroll
        for (int i = 0; i < P2_TPB / 32; i++) s += red[i];
        atomicAdd(out, s * (1.0f / BB));
    }
}

// ---------------------------------------------------------------------------
extern "C" void kernel_launch(void* const* d_in, const int* in_sizes, int n_in,
                              void* d_out, int out_size) {
    int ei = 0, gi = 1;
    // Defensive: identify inputs by size (embeddings = 67108864, gt = 2097152)
    if (n_in >= 2 && in_sizes[0] == BB * NPIX) { ei = 1; gi = 0; }

    const float* emb = (const float*)d_in[ei];
    const int*   gt  = (const int*)d_in[gi];
    float* out = (float*)d_out;

    k_pass1<<<dim3(P1_NCHUNK, 2, BB), 512>>>(emb, gt, out);
    k_finalize<<<BB, 256>>>(out);
    k_pass2<<<dim3(P2_BLOCKS, BB), P2_TPB>>>(emb, gt, out);
}

// round 13
// speedup vs baseline: 1.4021x; 1.0026x over previous
#include <cuda_runtime.h>
#include <cstddef>

// Problem constants (fixed by the reference)
#define BB 8
#define DD 32
#define NPIX 262144          // 512*512
#define KK 16

// Pass-1 tiling: 32 pixel-chunks x 2 d-groups x 8 images = 512 blocks
#define P1_CHUNK  8192
#define P1_NCHUNK (NPIX / P1_CHUNK)    // 32

// Pass-2 tiling: one float4 (4 pixels) per thread
#define P2_TPB    256
#define P2_BLOCKS (NPIX / 4 / P2_TPB)  // 256 blocks per image

// Scratch (no cudaMalloc allowed). Partials fully overwritten each launch.
__device__ float g_part[BB * P1_NCHUNK * KK * DD];   // per-chunk partial sums
__device__ float g_cntp[BB * P1_NCHUNK * KK];        // per-chunk partial counts
__device__ float g_counts[BB * KK];
__device__ float g_means[BB * KK * DD];

// ---------------------------------------------------------------------------
// Pass 1: per-image, per-chunk partial segment sums. (R12 verbatim.)
// Block = 512 threads = 16 warps; warp w owns plane d = dg*16 + w over the
// whole 8192-px chunk. Software-pipelined (distance 1). Embeddings loaded
// with DEFAULT policy (__ldg): pass1 is the first reader, leaving the stream
// L2-resident for pass2. Images processed z-major -> image 7 most resident.
// Per-lane privatized smem bins (stride 32): LDS/FADD/STS conflict-free.
// ---------------------------------------------------------------------------
__global__ __launch_bounds__(512) void k_pass1(const float* __restrict__ emb,
                                               const int* __restrict__ gt,
                                               float* out) {
    __shared__ float acc[16 * KK * 32];          // [w][k][lane]  32 KB
    __shared__ float cnt[KK * 32];               // [k][lane]      2 KB
    __shared__ unsigned int labw[P1_CHUNK / 4];  // packed 4x u8    8 KB

    const int b  = blockIdx.z;
    const int dg = blockIdx.y;                   // d group: 0 or 1
    const int c  = blockIdx.x;                   // chunk
    const int p0 = c * P1_CHUNK;
    const int tid = threadIdx.x;
    const int w   = tid >> 5;
    const int lane = tid & 31;
    const int d = dg * 16 + w;

    if (b == 0 && dg == 0 && c == 0 && tid == 0) out[0] = 0.0f;

    for (int j = tid; j < 16 * KK * 32; j += 512) acc[j] = 0.0f;
    if (tid < KK * 32) cnt[tid] = 0.0f;

    // Stage labels once (int4 -> packed u8x4): 2048 words
    const int4* g4 = (const int4*)(gt + (size_t)b * NPIX + p0);
    for (int j = tid; j < P1_CHUNK / 4; j += 512) {
        int4 t = g4[j];
        labw[j] = (unsigned)t.x | ((unsigned)t.y << 8) |
                  ((unsigned)t.z << 16) | ((unsigned)t.w << 24);
    }
    __syncthreads();

    const float4* e4 = (const float4*)(emb + ((size_t)(b * DD + d)) * NPIX + p0);
    const bool docnt = (dg == 0) && (w == 0);

    float* aw = acc + (w * KK) * 32 + lane;
    float* cw = cnt + lane;

    #define RMW(V, KW) do {                                             \
        unsigned kw_ = (KW);                                            \
        aw[(int)(kw_ & 15u) * 32]         += (V).x;                     \
        aw[(int)((kw_ >> 8) & 15u) * 32]  += (V).y;                     \
        aw[(int)((kw_ >> 16) & 15u) * 32] += (V).z;                     \
        aw[(int)(kw_ >> 24) * 32]         += (V).w;                     \
    } while (0)
    #define CNT(KW) do {                                                \
        unsigned kw_ = (KW);                                            \
        cw[(int)(kw_ & 15u) * 32]         += 1.0f;                      \
        cw[(int)((kw_ >> 8) & 15u) * 32]  += 1.0f;                      \
        cw[(int)((kw_ >> 16) & 15u) * 32] += 1.0f;                      \
        cw[(int)(kw_ >> 24) * 32]         += 1.0f;                      \
    } while (0)

    // 2048 float4s per plane-chunk per warp; 64 per lane, two per iteration.
    // Software pipeline, prefetch distance 1. Default-policy loads (L2-keep).
    float4 va = __ldg(&e4[lane]);
    float4 vb = __ldg(&e4[lane + 32]);
    unsigned ka = labw[lane];
    unsigned kb = labw[lane + 32];

    #pragma unroll 1
    for (int i = 0; i < 31; i++) {
        const int nidx = (i + 1) * 64 + lane;
        float4 na = __ldg(&e4[nidx]);
        float4 nb = __ldg(&e4[nidx + 32]);
        unsigned nka = labw[nidx];
        unsigned nkb = labw[nidx + 32];

        RMW(va, ka);
        RMW(vb, kb);
        if (docnt) { CNT(ka); CNT(kb); }

        va = na; vb = nb; ka = nka; kb = nkb;
    }
    RMW(va, ka);
    RMW(vb, kb);
    if (docnt) { CNT(ka); CNT(kb); }
    #undef RMW
    #undef CNT
    __syncwarp();

    // Epilogue: rows acc[w][k][0..31] are contiguous 128B. 2 lanes per k-row,
    // each reads 4 float4, sum, 1 shuffle, STG (no atomics).
    {
        const int k = lane >> 1;
        const int h = lane & 1;
        const float4* row = (const float4*)(acc + ((w * KK + k) << 5) + (h << 4));
        float4 r0 = row[0], r1 = row[1], r2 = row[2], r3 = row[3];
        float s = ((r0.x + r0.y) + (r0.z + r0.w)) + ((r1.x + r1.y) + (r1.z + r1.w))
                + ((r2.x + r2.y) + (r2.z + r2.w)) + ((r3.x + r3.y) + (r3.z + r3.w));
        s += __shfl_down_sync(0xffffffffu, s, 1);
        if (h == 0)
            g_part[(((b * P1_NCHUNK + c) * KK + k) * DD) + d] = s;
    }
    if (docnt) {
        const int k = lane >> 1;
        const int h = lane & 1;
        const float4* row = (const float4*)(cnt + (k << 5) + (h << 4));
        float4 r0 = row[0], r1 = row[1], r2 = row[2], r3 = row[3];
        float s = ((r0.x + r0.y) + (r0.z + r0.w)) + ((r1.x + r1.y) + (r1.z + r1.w))
                + ((r2.x + r2.y) + (r2.z + r2.w)) + ((r3.x + r3.y) + (r3.z + r3.w));
        s += __shfl_down_sync(0xffffffffu, s, 1);
        if (h == 0)
            g_cntp[(b * P1_NCHUNK + c) * KK + k] = s;
    }
}

// ---------------------------------------------------------------------------
// Finalize: reduce partials -> counts & means; pairwise push loss; reg loss.
// One block per image.
// ---------------------------------------------------------------------------
__global__ __launch_bounds__(256) void k_finalize(float* out) {
    __shared__ float m[KK * 33];    // padded means
    __shared__ float cs[KK];
    __shared__ float red[256];

    const int b = blockIdx.x;
    const int tid = threadIdx.x;

    if (tid < KK) {
        float s = 0.0f;
        #pragma unroll 4
        for (int c = 0; c < P1_NCHUNK; c++)
            s += g_cntp[(b * P1_NCHUNK + c) * KK + tid];
        float cv = fmaxf(s, 1.0f);
        cs[tid] = cv;
        g_counts[b * KK + tid] = cv;
    }
    __syncthreads();

    for (int j = tid; j < KK * DD; j += 256) {
        int k = j >> 5, d = j & 31;
        float s = 0.0f;
        #pragma unroll 4
        for (int c = 0; c < P1_NCHUNK; c++)
            s += g_part[(((b * P1_NCHUNK + c) * KK + k) * DD) + d];
        float mean = s / cs[k];
        g_means[(b * KK + k) * DD + d] = mean;
        m[k * 33 + d] = mean;
    }
    __syncthreads();

    // Pairwise hinge on cluster-mean distances: thread -> (i,j), upper tri only.
    const int i = tid >> 4;
    const int j = tid & 15;
    float contrib = 0.0f;
    if (j > i) {
        float d2 = 0.0f;
        #pragma unroll
        for (int d = 0; d < DD; d++) {
            float df = m[i * 33 + d] - m[j * 33 + d];
            d2 = fmaf(df, df, d2);
        }
        float pd = sqrtf(d2);             // i<j: diagonal eye irrelevant
        float h = fmaxf(3.0f - pd, 0.0f); // 2 * DIST_THETA = 3.0
        contrib = h * h;
    }

    float reg = 0.0f;
    if (tid < KK) {
        float n2 = 0.0f;
        #pragma unroll
        for (int d = 0; d < DD; d++) {
            float v = m[tid * 33 + d];
            n2 = fmaf(v, v, n2);
        }
        reg = sqrtf(n2);
    }

    red[tid] = contrib * (1.0f / (KK * (KK - 1))) + 0.001f * reg * (1.0f / KK);
    __syncthreads();
    for (int off = 128; off; off >>= 1) {
        if (tid < off) red[tid] += red[tid + off];
        __syncthreads();
    }
    if (tid == 0) atomicAdd(out, red[0] * (1.0f / BB));
}

// ---------------------------------------------------------------------------
// Pass 2: per-pixel hinge variance loss, folded directly into the scalar.
// REVERSED traversal: first-scheduled blocks (low bid) read image 7 / the
// highest chunks -- exactly the lines pass1 wrote LAST and which are still
// L2-resident -- harvesting the reuse before pass2's own fills evict it.
// __ldcs (evict-first): pass2 is the last consumer.
// ---------------------------------------------------------------------------
__global__ __launch_bounds__(P2_TPB) void k_pass2(const float* __restrict__ emb,
                                                  const int* __restrict__ gt,
                                                  float* out) {
    __shared__ float m[KK * 33];
    __shared__ float wk[KK];
    __shared__ float red[P2_TPB / 32];

    const int b  = (BB - 1) - blockIdx.y;                 // image reversal
    const int xr = (P2_BLOCKS - 1) - blockIdx.x;          // chunk reversal
    const int tid = threadIdx.x;
    const int lane = tid & 31;
    const int w = tid >> 5;
    const int p4 = xr * P2_TPB + tid;            // float4 index

    for (int j = tid; j < KK * DD; j += P2_TPB)
        m[(j / DD) * 33 + (j % DD)] = g_means[b * KK * DD + j];
    if (tid < KK)
        wk[tid] = 1.0f / ((float)KK * fmaxf(g_counts[b * KK + tid], 1.0f));
    __syncthreads();

    const float4* e4 = (const float4*)(emb + (size_t)b * DD * NPIX);
    const int4 kk = ((const int4*)(gt + (size_t)b * NPIX))[p4];

    const float* m0 = m + kk.x * 33;
    const float* m1 = m + kk.y * 33;
    const float* m2 = m + kk.z * 33;
    const float* m3 = m + kk.w * 33;

    float a0 = 0.0f, a1 = 0.0f, a2 = 0.0f, a3 = 0.0f;
    #pragma unroll
    for (int g = 0; g < 4; g++) {
        float4 v[8];
        #pragma unroll
        for (int j = 0; j < 8; j++)
            v[j] = __ldcs(&e4[(size_t)(g * 8 + j) * (NPIX / 4) + p4]);
        #pragma unroll
        for (int j = 0; j < 8; j++) {
            const int d = g * 8 + j;
            float t;
            t = v[j].x - m0[d]; a0 = fmaf(t, t, a0);
            t = v[j].y - m1[d]; a1 = fmaf(t, t, a1);
            t = v[j].z - m2[d]; a2 = fmaf(t, t, a2);
            t = v[j].w - m3[d]; a3 = fmaf(t, t, a3);
        }
    }

    float h, lacc = 0.0f;
    h = fmaxf(sqrtf(a0) - 0.5f, 0.0f); lacc = fmaf(h * h, wk[kk.x], lacc);
    h = fmaxf(sqrtf(a1) - 0.5f, 0.0f); lacc = fmaf(h * h, wk[kk.y], lacc);
    h = fmaxf(sqrtf(a2) - 0.5f, 0.0f); lacc = fmaf(h * h, wk[kk.z], lacc);
    h = fmaxf(sqrtf(a3) - 0.5f, 0.0f); lacc = fmaf(h * h, wk[kk.w], lacc);

    #pragma unroll
    for (int off = 16; off; off >>= 1)
        lacc += __shfl_down_sync(0xffffffffu, lacc, off);
    if (lane == 0) red[w] = lacc;
    __syncthreads();
    if (tid == 0) {
        float s = 0.0f;
        #pragma unroll
        for (int i = 0; i < P2_TPB / 32; i++) s += red[i];
        atomicAdd(out, s * (1.0f / BB));
    }
}

// ---------------------------------------------------------------------------
extern "C" void kernel_launch(void* const* d_in, const int* in_sizes, int n_in,
                              void* d_out, int out_size) {
    int ei = 0, gi = 1;
    // Defensive: identify inputs by size (embeddings = 67108864, gt = 2097152)
    if (n_in >= 2 && in_sizes[0] == BB * NPIX) { ei = 1; gi = 0; }

    const float* emb = (const float*)d_in[ei];
    const int*   gt  = (const int*)d_in[gi];
    float* out = (float*)d_out;

    k_pass1<<<dim3(P1_NCHUNK, 2, BB), 512>>>(emb, gt, out);
    k_finalize<<<BB, 256>>>(out);
    k_pass2<<<dim3(P2_BLOCKS, BB), P2_TPB>>>(emb, gt, out);
}